// round 3
// baseline (speedup 1.0000x reference)
#include <cuda_runtime.h>
#include <cstdint>
#include <cstddef>

// Irrep-wise linear: y[n, block o,d] = alpha * sum_i x[n, block i,d] * W[i,o]
// Blocks: (mul=128,d=1) cols [0,128), (mul=64,d=3) cols [128,320), (mul=32,d=5) cols [320,480)
// Strategy: packed f32x2 FMA over output pairs (o,o+1): W pairs load directly as
// 64-bit LDS operands (contiguous in o), x broadcast-packed once per k.

#define THREADS 512
#define CTA_ROWS 64
#define DIM 480

// smem float offsets
#define W0S_OFF 0         // 128*128 = 16384
#define W1S_OFF 16384     // 64*64   = 4096
#define W2S_OFF 20480     // 32*32   = 1024
#define XS_OFF  21504     // max tile 64*97 = 6208
#define SMEM_FLOATS (21504 + 6208)

static __device__ __forceinline__ unsigned long long ffma2(
    unsigned long long a, unsigned long long b, unsigned long long c) {
    unsigned long long d;
    asm("fma.rn.f32x2 %0, %1, %2, %3;" : "=l"(d) : "l"(a), "l"(b), "l"(c));
    return d;
}

static __device__ __forceinline__ unsigned long long pack2(float x) {
    unsigned long long d;
    unsigned int u = __float_as_uint(x);
    asm("mov.b64 %0, {%1, %1};" : "=l"(d) : "r"(u));
    return d;
}

static __device__ __forceinline__ float2 unpack2(unsigned long long v) {
    unsigned int lo, hi;
    asm("mov.b64 {%0, %1}, %2;" : "=r"(lo), "=r"(hi) : "l"(v));
    return make_float2(__uint_as_float(lo), __uint_as_float(hi));
}

// Stage CTA_ROWS x (CW4*4) float tile from global x (row-major [N,DIM]) into Xs
// with per-row stride XST floats (odd -> conflict-free column reads).
template <int CW4, int XST>
static __device__ __forceinline__ void stage_tile(
    const float* __restrict__ x, float* __restrict__ Xs,
    int rowbase, int nrows, int gcol) {
    for (int idx = threadIdx.x; idx < CTA_ROWS * CW4; idx += THREADS) {
        int r = idx / CW4;
        int q = idx - r * CW4;
        int gr = rowbase + r;
        if (gr >= nrows) gr = nrows - 1;  // clamp (partial last CTA); stores are guarded
        float4 v = *reinterpret_cast<const float4*>(x + (size_t)gr * DIM + gcol + q * 4);
        float* dst = Xs + r * XST + q * 4;
        dst[0] = v.x; dst[1] = v.y; dst[2] = v.z; dst[3] = v.w;
    }
}

__global__ void __launch_bounds__(THREADS, 1)
irrep_linear_kernel(const float* __restrict__ x,
                    const float* __restrict__ W0,
                    const float* __restrict__ W1,
                    const float* __restrict__ W2,
                    float* __restrict__ y,
                    int nrows) {
    extern __shared__ float smem[];
    float* W0s = smem + W0S_OFF;
    float* W1s = smem + W1S_OFF;
    float* W2s = smem + W2S_OFF;
    float* Xs  = smem + XS_OFF;

    const int tid = threadIdx.x;

    // ---- Load weights into smem, folding in alpha = 1/sqrt(mul_in) ----
    {
        const float a0 = 0.08838834764831845f;   // 1/sqrt(128)
        for (int i = tid; i < 128 * 128; i += THREADS) W0s[i] = W0[i] * a0;
        const float a1 = 0.125f;                  // 1/sqrt(64)
        for (int i = tid; i < 64 * 64; i += THREADS) W1s[i] = W1[i] * a1;
        const float a2 = 0.17677669529663689f;    // 1/sqrt(32)
        for (int i = tid; i < 32 * 32; i += THREADS) W2s[i] = W2[i] * a2;
    }
    // (visibility ordered by the first __syncthreads below)

    const int row = tid >> 3;      // 0..63
    const int og  = tid & 7;       // 0..7
    const int rowbase = blockIdx.x * CTA_ROWS;
    const int grow = rowbase + row;
    const bool valid = (grow < nrows);
    float* yrow = y + (size_t)grow * DIM;

    // ================= Phase A: block0 (mul=128, d=1), cols [0,128) =================
    // og covers outputs [og*16, og*16+16) -> 8 f32x2 accumulators over o-pairs.
    {
        unsigned long long acc[8];
#pragma unroll
        for (int j = 0; j < 8; ++j) acc[j] = 0ull;

#pragma unroll 1
        for (int c = 0; c < 4; ++c) {            // K chunks of 32
            __syncthreads();
            stage_tile<8, 33>(x, Xs, rowbase, nrows, c * 32);
            __syncthreads();
            const float* xr = Xs + row * 33;
            const float* wbase = W0s + (c * 32) * 128 + og * 16;
#pragma unroll
            for (int k = 0; k < 32; ++k) {
                unsigned long long xx = pack2(xr[k]);
                const ulonglong2* wp =
                    reinterpret_cast<const ulonglong2*>(wbase + k * 128);
                ulonglong2 wA = wp[0];
                ulonglong2 wB = wp[1];
                ulonglong2 wC = wp[2];
                ulonglong2 wD = wp[3];
                acc[0] = ffma2(xx, wA.x, acc[0]);
                acc[1] = ffma2(xx, wA.y, acc[1]);
                acc[2] = ffma2(xx, wB.x, acc[2]);
                acc[3] = ffma2(xx, wB.y, acc[3]);
                acc[4] = ffma2(xx, wC.x, acc[4]);
                acc[5] = ffma2(xx, wC.y, acc[5]);
                acc[6] = ffma2(xx, wD.x, acc[6]);
                acc[7] = ffma2(xx, wD.y, acc[7]);
            }
        }
        if (valid) {
            float4* yo = reinterpret_cast<float4*>(yrow + og * 16);
#pragma unroll
            for (int j = 0; j < 4; ++j) {
                float2 p0 = unpack2(acc[2 * j]);
                float2 p1 = unpack2(acc[2 * j + 1]);
                yo[j] = make_float4(p0.x, p0.y, p1.x, p1.y);
            }
        }
    }

    // ================= Phase B: block1 (mul=64, d=3), cols [128,320) =================
    // og covers 8 output channels x 3 d -> 12 f32x2 accumulators acc[d*4+m],
    // m over o-pairs (og*8+2m, og*8+2m+1).
    {
        unsigned long long acc[12];
#pragma unroll
        for (int j = 0; j < 12; ++j) acc[j] = 0ull;

#pragma unroll 1
        for (int c = 0; c < 2; ++c) {            // i chunks of 32 (96 cols each)
            __syncthreads();
            stage_tile<24, 97>(x, Xs, rowbase, nrows, 128 + c * 96);
            __syncthreads();
            const float* xr = Xs + row * 97;
            const float* wbase = W1s + og * 8;
#pragma unroll
            for (int i = 0; i < 32; ++i) {
                int gi = c * 32 + i;
                unsigned long long x0 = pack2(xr[i * 3 + 0]);
                unsigned long long x1 = pack2(xr[i * 3 + 1]);
                unsigned long long x2 = pack2(xr[i * 3 + 2]);
                const ulonglong2* wp =
                    reinterpret_cast<const ulonglong2*>(wbase + gi * 64);
                ulonglong2 wA = wp[0];
                ulonglong2 wB = wp[1];
                acc[0]  = ffma2(x0, wA.x, acc[0]);
                acc[1]  = ffma2(x0, wA.y, acc[1]);
                acc[2]  = ffma2(x0, wB.x, acc[2]);
                acc[3]  = ffma2(x0, wB.y, acc[3]);
                acc[4]  = ffma2(x1, wA.x, acc[4]);
                acc[5]  = ffma2(x1, wA.y, acc[5]);
                acc[6]  = ffma2(x1, wB.x, acc[6]);
                acc[7]  = ffma2(x1, wB.y, acc[7]);
                acc[8]  = ffma2(x2, wA.x, acc[8]);
                acc[9]  = ffma2(x2, wA.y, acc[9]);
                acc[10] = ffma2(x2, wB.x, acc[10]);
                acc[11] = ffma2(x2, wB.y, acc[11]);
            }
        }
        if (valid) {
            // lane's output span: cols [128 + og*24, +24), layout o_local*3 + d
            float vals[24];
#pragma unroll
            for (int m = 0; m < 4; ++m) {
#pragma unroll
                for (int d = 0; d < 3; ++d) {
                    float2 p = unpack2(acc[d * 4 + m]);
                    vals[(2 * m) * 3 + d]     = p.x;
                    vals[(2 * m + 1) * 3 + d] = p.y;
                }
            }
            float4* yo = reinterpret_cast<float4*>(yrow + 128 + og * 24);
#pragma unroll
            for (int j = 0; j < 6; ++j)
                yo[j] = make_float4(vals[4 * j], vals[4 * j + 1],
                                    vals[4 * j + 2], vals[4 * j + 3]);
        }
    }

    // ================= Phase C: block2 (mul=32, d=5), cols [320,480) =================
    // og covers 4 output channels x 5 d -> 10 f32x2 accumulators acc[d*2+m].
    {
        unsigned long long acc[10];
#pragma unroll
        for (int j = 0; j < 10; ++j) acc[j] = 0ull;

#pragma unroll 1
        for (int c = 0; c < 2; ++c) {            // i chunks of 16 (80 cols each)
            __syncthreads();
            stage_tile<20, 81>(x, Xs, rowbase, nrows, 320 + c * 80);
            __syncthreads();
            const float* xr = Xs + row * 81;
            const float* wbase = W2s + og * 4;
#pragma unroll
            for (int i = 0; i < 16; ++i) {
                int gi = c * 16 + i;
                unsigned long long xd0 = pack2(xr[i * 5 + 0]);
                unsigned long long xd1 = pack2(xr[i * 5 + 1]);
                unsigned long long xd2 = pack2(xr[i * 5 + 2]);
                unsigned long long xd3 = pack2(xr[i * 5 + 3]);
                unsigned long long xd4 = pack2(xr[i * 5 + 4]);
                ulonglong2 w = *reinterpret_cast<const ulonglong2*>(wbase + gi * 32);
                acc[0] = ffma2(xd0, w.x, acc[0]);
                acc[1] = ffma2(xd0, w.y, acc[1]);
                acc[2] = ffma2(xd1, w.x, acc[2]);
                acc[3] = ffma2(xd1, w.y, acc[3]);
                acc[4] = ffma2(xd2, w.x, acc[4]);
                acc[5] = ffma2(xd2, w.y, acc[5]);
                acc[6] = ffma2(xd3, w.x, acc[6]);
                acc[7] = ffma2(xd3, w.y, acc[7]);
                acc[8] = ffma2(xd4, w.x, acc[8]);
                acc[9] = ffma2(xd4, w.y, acc[9]);
            }
        }
        if (valid) {
            // lane's output span: cols [320 + og*20, +20), layout o_local*5 + d
            float vals[20];
#pragma unroll
            for (int m = 0; m < 2; ++m) {
#pragma unroll
                for (int d = 0; d < 5; ++d) {
                    float2 p = unpack2(acc[d * 2 + m]);
                    vals[(2 * m) * 5 + d]     = p.x;
                    vals[(2 * m + 1) * 5 + d] = p.y;
                }
            }
            float4* yo = reinterpret_cast<float4*>(yrow + 320 + og * 20);
#pragma unroll
            for (int j = 0; j < 5; ++j)
                yo[j] = make_float4(vals[4 * j], vals[4 * j + 1],
                                    vals[4 * j + 2], vals[4 * j + 3]);
        }
    }
}

extern "C" void kernel_launch(void* const* d_in, const int* in_sizes, int n_in,
                              void* d_out, int out_size) {
    const float* x  = (const float*)d_in[0];
    const float* W0 = (const float*)d_in[1];
    const float* W1 = (const float*)d_in[2];
    const float* W2 = (const float*)d_in[3];
    float* y = (float*)d_out;

    int nrows = in_sizes[0] / DIM;                 // 200000
    int grid = (nrows + CTA_ROWS - 1) / CTA_ROWS;  // 3125

    size_t smem_bytes = SMEM_FLOATS * sizeof(float);  // ~108 KB
    cudaFuncSetAttribute(irrep_linear_kernel,
                         cudaFuncAttributeMaxDynamicSharedMemorySize,
                         (int)smem_bytes);

    irrep_linear_kernel<<<grid, THREADS, smem_bytes>>>(x, W0, W1, W2, y, nrows);
}

// round 4
// speedup vs baseline: 3.3191x; 3.3191x over previous
#include <cuda_runtime.h>
#include <cstdint>
#include <cstddef>

// Irrep-wise linear: y[n, block o,d] = alpha * sum_i x[n, block i,d] * W[i,o]
// Blocks: (mul=128,d=1) cols [0,128), (mul=64,d=3) cols [128,320), (mul=32,d=5) cols [320,480)
//
// Register-tiled FFMA2 GEMM: per-thread tile 8 rows x 8 outs (phase A),
// output-paired f32x2 accumulators; W vector-loaded from smem (conflict-free),
// x scalar-broadcast from row-major padded smem tile.

#define THREADS 256
#define CTA_ROWS 128
#define DIM 480

// smem float offsets
#define W0S_OFF 0          // 128*128 = 16384
#define W1S_OFF 16384      // 64*64   = 4096
#define W2S_OFF 20480      // 32*32   = 1024
#define XS_OFF  21504      // max chunk 128*36 = 4608
#define SMEM_FLOATS (21504 + 4608)   // 26112 floats = 104448 B  -> 2 CTAs/SM

static __device__ __forceinline__ unsigned long long ffma2(
    unsigned long long a, unsigned long long b, unsigned long long c) {
    unsigned long long d;
    asm("fma.rn.f32x2 %0, %1, %2, %3;" : "=l"(d) : "l"(a), "l"(b), "l"(c));
    return d;
}

static __device__ __forceinline__ unsigned long long pack2(float x) {
    unsigned long long d;
    unsigned int u = __float_as_uint(x);
    asm("mov.b64 %0, {%1, %1};" : "=l"(d) : "r"(u));
    return d;
}

static __device__ __forceinline__ float2 unpack2(unsigned long long v) {
    unsigned int lo, hi;
    asm("mov.b64 {%0, %1}, %2;" : "=r"(lo), "=r"(hi) : "l"(v));
    return make_float2(__uint_as_float(lo), __uint_as_float(hi));
}

__global__ void __launch_bounds__(THREADS, 2)
irrep_linear_kernel(const float* __restrict__ x,
                    const float* __restrict__ W0,
                    const float* __restrict__ W1,
                    const float* __restrict__ W2,
                    float* __restrict__ y,
                    int nrows) {
    extern __shared__ float smem[];
    float* W0s = smem + W0S_OFF;
    float* W1s = smem + W1S_OFF;
    float* W2s = smem + W2S_OFF;
    float* Xs  = smem + XS_OFF;

    const int tid = threadIdx.x;
    const int rowbase = blockIdx.x * CTA_ROWS;

    // ---- Load weights into smem, folding in alpha = 1/sqrt(mul_in) ----
    {
        const float a0 = 0.08838834764831845f;   // 1/sqrt(128)
        for (int i = tid; i < 128 * 128; i += THREADS) W0s[i] = W0[i] * a0;
        const float a1 = 0.125f;                  // 1/sqrt(64)
        for (int i = tid; i < 64 * 64; i += THREADS) W1s[i] = W1[i] * a1;
        const float a2 = 0.17677669529663689f;    // 1/sqrt(32)
        for (int i = tid; i < 32 * 32; i += THREADS) W2s[i] = W2[i] * a2;
    }
    // ordered by the first __syncthreads in phase A

    // ================= Phase A: block0 (mul=128, d=1), cols [0,128) =================
    // Tile: 8 rows x 8 outs. rg = tid>>4 (16 groups of 8 rows = 128),
    // og = tid&15 (16 groups of 8 outs = 128). acc[r][p], p = o-pair.
    {
        const int rg = tid >> 4;
        const int og = tid & 15;
        unsigned long long acc[8][4];
#pragma unroll
        for (int r = 0; r < 8; ++r)
#pragma unroll
            for (int p = 0; p < 4; ++p) acc[r][p] = 0ull;

        const int xbase = (rg * 8) * 36;

#pragma unroll 1
        for (int c = 0; c < 4; ++c) {            // 4 chunks of 32 k
            __syncthreads();
            // stage [128 rows][32 cols] at stride 36 (float4 conflict-free)
            for (int idx = tid; idx < 128 * 8; idx += THREADS) {
                int r = idx >> 3, q = idx & 7;
                int gr = rowbase + r;
                if (gr >= nrows) gr = nrows - 1;
                float4 v = *reinterpret_cast<const float4*>(
                    x + (size_t)gr * DIM + c * 32 + q * 4);
                *reinterpret_cast<float4*>(Xs + r * 36 + q * 4) = v;
            }
            __syncthreads();

            const float* wb = W0s + (c * 32) * 128 + og * 8;
#pragma unroll 4
            for (int k = 0; k < 32; ++k) {
                ulonglong2 wA = *reinterpret_cast<const ulonglong2*>(wb + k * 128);
                ulonglong2 wB = *reinterpret_cast<const ulonglong2*>(wb + k * 128 + 4);
#pragma unroll
                for (int r = 0; r < 8; ++r) {
                    unsigned long long xp = pack2(Xs[xbase + r * 36 + k]);
                    acc[r][0] = ffma2(xp, wA.x, acc[r][0]);
                    acc[r][1] = ffma2(xp, wA.y, acc[r][1]);
                    acc[r][2] = ffma2(xp, wB.x, acc[r][2]);
                    acc[r][3] = ffma2(xp, wB.y, acc[r][3]);
                }
            }
        }
        // epilogue: 8 rows x 8 outs -> two float4 per row
#pragma unroll
        for (int r = 0; r < 8; ++r) {
            int grow = rowbase + rg * 8 + r;
            if (grow < nrows) {
                float4* yo = reinterpret_cast<float4*>(y + (size_t)grow * DIM + og * 8);
                float2 p0 = unpack2(acc[r][0]);
                float2 p1 = unpack2(acc[r][1]);
                float2 p2 = unpack2(acc[r][2]);
                float2 p3 = unpack2(acc[r][3]);
                yo[0] = make_float4(p0.x, p0.y, p1.x, p1.y);
                yo[1] = make_float4(p2.x, p2.y, p3.x, p3.y);
            }
        }
    }

    // ================= Phase B: block1 (mul=64, d=3), cols [128,320) =================
    // GEMM rows = (n, dd): two half passes of 64 n each. Tile: 6 rows (2n x 3dd) x 8 outs.
    // rg = tid>>3 (32 -> n-pair), og = tid&7 (8 groups of 8 outs = 64).
    {
        const int rg = tid >> 3;
        const int og = tid & 7;

#pragma unroll 1
        for (int h = 0; h < 2; ++h) {
            unsigned long long acc[6][4];
#pragma unroll
            for (int a = 0; a < 6; ++a)
#pragma unroll
                for (int p = 0; p < 4; ++p) acc[a][p] = 0ull;

#pragma unroll 1
            for (int c = 0; c < 8; ++c) {        // 8 chunks of 8 i (24 cols)
                __syncthreads();
                // stage [64 n][24 cols] at stride 28
                for (int idx = tid; idx < 64 * 6; idx += THREADS) {
                    int r = idx / 6, q = idx - r * 6;
                    int gr = rowbase + h * 64 + r;
                    if (gr >= nrows) gr = nrows - 1;
                    float4 v = *reinterpret_cast<const float4*>(
                        x + (size_t)gr * DIM + 128 + c * 24 + q * 4);
                    *reinterpret_cast<float4*>(Xs + r * 28 + q * 4) = v;
                }
                __syncthreads();

                const float* wb = W1s + (c * 8) * 64 + og * 8;
                const float* xb = Xs + (rg * 2) * 28;
#pragma unroll
                for (int i = 0; i < 8; ++i) {
                    ulonglong2 wA = *reinterpret_cast<const ulonglong2*>(wb + i * 64);
                    ulonglong2 wB = *reinterpret_cast<const ulonglong2*>(wb + i * 64 + 4);
#pragma unroll
                    for (int e = 0; e < 2; ++e) {
#pragma unroll
                        for (int dd = 0; dd < 3; ++dd) {
                            unsigned long long xp = pack2(xb[e * 28 + i * 3 + dd]);
                            int a = e * 3 + dd;
                            acc[a][0] = ffma2(xp, wA.x, acc[a][0]);
                            acc[a][1] = ffma2(xp, wA.y, acc[a][1]);
                            acc[a][2] = ffma2(xp, wB.x, acc[a][2]);
                            acc[a][3] = ffma2(xp, wB.y, acc[a][3]);
                        }
                    }
                }
            }
            // epilogue: per n (2), 24 consecutive floats at col 128 + og*24
#pragma unroll
            for (int e = 0; e < 2; ++e) {
                int grow = rowbase + h * 64 + rg * 2 + e;
                if (grow < nrows) {
                    float vals[24];
#pragma unroll
                    for (int m = 0; m < 4; ++m) {
#pragma unroll
                        for (int dd = 0; dd < 3; ++dd) {
                            float2 p = unpack2(acc[e * 3 + dd][m]);
                            vals[(2 * m) * 3 + dd]     = p.x;
                            vals[(2 * m + 1) * 3 + dd] = p.y;
                        }
                    }
                    float4* yo = reinterpret_cast<float4*>(
                        y + (size_t)grow * DIM + 128 + og * 24);
#pragma unroll
                    for (int j = 0; j < 6; ++j)
                        yo[j] = make_float4(vals[4 * j], vals[4 * j + 1],
                                            vals[4 * j + 2], vals[4 * j + 3]);
                }
            }
        }
    }

    // ================= Phase C: block2 (mul=32, d=5), cols [320,480) =================
    // GEMM rows = (n, dd): two half passes of 64 n. Tile: 5 rows (1n x 5dd) x 8 outs.
    // rg = tid>>2 (64 -> n), og = tid&3 (4 groups of 8 outs = 32).
    {
        const int rg = tid >> 2;
        const int og = tid & 3;

#pragma unroll 1
        for (int h = 0; h < 2; ++h) {
            unsigned long long acc[5][4];
#pragma unroll
            for (int a = 0; a < 5; ++a)
#pragma unroll
                for (int p = 0; p < 4; ++p) acc[a][p] = 0ull;

#pragma unroll 1
            for (int c = 0; c < 4; ++c) {        // 4 chunks of 8 i (40 cols)
                __syncthreads();
                // stage [64 n][40 cols] at stride 44
                for (int idx = tid; idx < 64 * 10; idx += THREADS) {
                    int r = idx / 10, q = idx - r * 10;
                    int gr = rowbase + h * 64 + r;
                    if (gr >= nrows) gr = nrows - 1;
                    float4 v = *reinterpret_cast<const float4*>(
                        x + (size_t)gr * DIM + 320 + c * 40 + q * 4);
                    *reinterpret_cast<float4*>(Xs + r * 44 + q * 4) = v;
                }
                __syncthreads();

                const float* wb = W2s + (c * 8) * 32 + og * 8;
                const float* xb = Xs + rg * 44;
#pragma unroll
                for (int i = 0; i < 8; ++i) {
                    ulonglong2 wA = *reinterpret_cast<const ulonglong2*>(wb + i * 32);
                    ulonglong2 wB = *reinterpret_cast<const ulonglong2*>(wb + i * 32 + 4);
#pragma unroll
                    for (int dd = 0; dd < 5; ++dd) {
                        unsigned long long xp = pack2(xb[i * 5 + dd]);
                        acc[dd][0] = ffma2(xp, wA.x, acc[dd][0]);
                        acc[dd][1] = ffma2(xp, wA.y, acc[dd][1]);
                        acc[dd][2] = ffma2(xp, wB.x, acc[dd][2]);
                        acc[dd][3] = ffma2(xp, wB.y, acc[dd][3]);
                    }
                }
            }
            // epilogue: 40 consecutive floats at col 320 + og*40
            {
                int grow = rowbase + h * 64 + rg;
                if (grow < nrows) {
                    float vals[40];
#pragma unroll
                    for (int m = 0; m < 4; ++m) {
#pragma unroll
                        for (int dd = 0; dd < 5; ++dd) {
                            float2 p = unpack2(acc[dd][m]);
                            vals[(2 * m) * 5 + dd]     = p.x;
                            vals[(2 * m + 1) * 5 + dd] = p.y;
                        }
                    }
                    float4* yo = reinterpret_cast<float4*>(
                        y + (size_t)grow * DIM + 320 + og * 40);
#pragma unroll
                    for (int j = 0; j < 10; ++j)
                        yo[j] = make_float4(vals[4 * j], vals[4 * j + 1],
                                            vals[4 * j + 2], vals[4 * j + 3]);
                }
            }
        }
    }
}

extern "C" void kernel_launch(void* const* d_in, const int* in_sizes, int n_in,
                              void* d_out, int out_size) {
    const float* x  = (const float*)d_in[0];
    const float* W0 = (const float*)d_in[1];
    const float* W1 = (const float*)d_in[2];
    const float* W2 = (const float*)d_in[3];
    float* y = (float*)d_out;

    int nrows = in_sizes[0] / DIM;                     // 200000
    int grid = (nrows + CTA_ROWS - 1) / CTA_ROWS;      // 1563

    size_t smem_bytes = SMEM_FLOATS * sizeof(float);   // 104448 B -> 2 CTAs/SM
    cudaFuncSetAttribute(irrep_linear_kernel,
                         cudaFuncAttributeMaxDynamicSharedMemorySize,
                         (int)smem_bytes);

    irrep_linear_kernel<<<grid, THREADS, smem_bytes>>>(x, W0, W1, W2, y, nrows);
}